// round 12
// baseline (speedup 1.0000x reference)
#include <cuda_runtime.h>
#include <cstdint>

// Shapes fixed: B=16, N=64, D=E=256. Output: [new_nodes 1024x256 | h 65536x256] f32.
#define NROWS     1024
#define OUT_H_OFF (NROWS * 256)

// ---------------- device scratch ----------------
__device__ float g_PQ[NROWS * 512];   // P = nodes@W1 + b_in | Q = nodes@W2
__device__ float g_res[NROWS * 256];  // attn-weighted residual

// ---------------- helpers ----------------
__device__ __forceinline__ void mma_tf32(float* c, const uint32_t* a, const uint32_t* b) {
    asm volatile(
        "mma.sync.aligned.m16n8k8.row.col.f32.tf32.tf32.f32 "
        "{%0,%1,%2,%3}, {%4,%5,%6,%7}, {%8,%9}, {%0,%1,%2,%3};"
        : "+f"(c[0]), "+f"(c[1]), "+f"(c[2]), "+f"(c[3])
        : "r"(a[0]), "r"(a[1]), "r"(a[2]), "r"(a[3]), "r"(b[0]), "r"(b[1]));
}
__device__ __forceinline__ uint32_t smem_u32(const void* p) {
    uint32_t a;
    asm("{ .reg .u64 t; cvta.to.shared.u64 t, %1; cvt.u32.u64 %0, t; }" : "=r"(a) : "l"(p));
    return a;
}
#define CP_ASYNC16(dst, src) \
    asm volatile("cp.async.cg.shared.global [%0], [%1], 16;" :: "r"(dst), "l"(src))
#define CP_COMMIT()  asm volatile("cp.async.commit_group;" ::: "memory")
#define CP_WAIT1()   asm volatile("cp.async.wait_group 1;" ::: "memory")
#define CP_WAIT0()   asm volatile("cp.async.wait_group 0;" ::: "memory")

// ---------------- smem layout for gnn_main6 (bytes) ----------------
// E tiles m-major [64][36]; W tiles k-major [32][264] (stride 264 => bank-clean)
#define EC0_OFF   0        // 9216
#define EC1_OFF   9216     // 9216 -> 18432
#define WC0_OFF   18432    // 32*264*4 = 33792 -> 52224
#define WC1_OFF   52224    // 33792 -> 86016
#define HS_OFF    0        // epilogue overlay: [64][260] f = 66560 (< 86016)
#define PS_OFF    86016    // 256 f
#define WCS_OFF   87040    // 256 f
#define CP_OFF    88064    // [4][64] f
#define COEF_OFF  89088    // 64 f
#define ATTN_OFF  89344    // 64 f
#define SMEM_BYTES 89600

// ===========================================================================
// Kernel A: PQ = [nodes@W1 + b_in | nodes@W2] only (W3 handled raw by gnn).
// 32x32 tiles, grid 512 (32 rb x 16 cb), 256 threads, ~17KB smem ->
// 4+ resident CTAs/SM so per-chunk latency overlaps across CTAs.
// As stride = 36 (multiple of 4: float4 reads stay 16B-aligned; reads are
// warp-uniform broadcasts so banking is irrelevant).
// ===========================================================================
__global__ __launch_bounds__(256) void prep_pq(
    const float* __restrict__ nodes, const float* __restrict__ W_in, const float* __restrict__ b_in)
{
    __shared__ float As[64 * 36];   // [k][r] transposed A, 32 rows used
    __shared__ float Bs[64 * 32];   // [k][c]
    const int tid = threadIdx.x;
    const int cb = blockIdx.x & 15;         // 0..15 col block (32 cols)
    const int rb = blockIdx.x >> 4;         // 0..31 row block (32 rows)
    const int kadd = (cb >= 8) ? 256 : 0;   // W2 half uses W_in rows 256..511
    const int cbase = (cb & 7) * 32;
    const int ty = tid >> 5;                // warp 0..7 -> rows ty*4..+3
    const int tx = tid & 31;                // lane -> col tx

    float4 apf[2], bpf[2];
    auto loadA = [&](int kc) {
#pragma unroll
        for (int u = 0; u < 2; ++u) {
            int idx = tid * 2 + u;            // 0..511
            int r = idx >> 4, k4 = (idx & 15) << 2;
            apf[u] = *(const float4*)(nodes + (size_t)(rb * 32 + r) * 256 + kc * 64 + k4);
        }
    };
    auto loadB = [&](int kc) {
#pragma unroll
        for (int u = 0; u < 2; ++u) {
            int idx = tid * 2 + u;            // 0..511
            int k = idx >> 3, c4 = (idx & 7) << 2;
            bpf[u] = *(const float4*)(W_in + (size_t)(kadd + kc * 64 + k) * 256 + cbase + c4);
        }
    };

    float acc[4];
    acc[0] = acc[1] = acc[2] = acc[3] = 0.f;

    loadA(0);
    loadB(0);

    for (int kc = 0; kc < 4; ++kc) {
#pragma unroll
        for (int u = 0; u < 2; ++u) {
            int idx = tid * 2 + u, r = idx >> 4, k4 = (idx & 15) << 2;
            As[(k4 + 0) * 36 + r] = apf[u].x; As[(k4 + 1) * 36 + r] = apf[u].y;
            As[(k4 + 2) * 36 + r] = apf[u].z; As[(k4 + 3) * 36 + r] = apf[u].w;
        }
#pragma unroll
        for (int u = 0; u < 2; ++u) {
            int idx = tid * 2 + u, k = idx >> 3, c4 = (idx & 7) << 2;
            *(float4*)(Bs + k * 32 + c4) = bpf[u];
        }
        __syncthreads();

        if (kc < 3) { loadA(kc + 1); loadB(kc + 1); }

#pragma unroll 8
        for (int kk = 0; kk < 64; ++kk) {
            float4 av = *(const float4*)(As + kk * 36 + ty * 4);  // warp-uniform bcast
            float bv = Bs[kk * 32 + tx];                          // conflict-free
            acc[0] += av.x * bv;
            acc[1] += av.y * bv;
            acc[2] += av.z * bv;
            acc[3] += av.w * bv;
        }
        __syncthreads();
    }

    float bias = (cb < 8) ? b_in[cbase + tx] : 0.f;
#pragma unroll
    for (int ri = 0; ri < 4; ++ri) {
        int r = rb * 32 + ty * 4 + ri;
        g_PQ[(size_t)r * 512 + cb * 32 + tx] = acc[ri] + bias;
    }
}

// ===========================================================================
// Kernel B: tf32 mma GEMM (H = E@W3 per (b,i)) + fused attention.
// grid 1024, 256 threads. cp.async double-buffered. W staged K-MAJOR
// directly from W_in (raw f32 bits -> tf32 truncation), [32][264] bank-clean.
// ===========================================================================
__global__ __launch_bounds__(256) void gnn_main6(
    const float* __restrict__ edges,
    const float* __restrict__ W_in,
    const float* __restrict__ W_coef,
    float* __restrict__ out)
{
    extern __shared__ char sm[];
    const uint32_t sbase = smem_u32(sm);
    float* hs   = (float*)(sm + HS_OFF);
    float* ps   = (float*)(sm + PS_OFF);
    float* wcs  = (float*)(sm + WCS_OFF);
    float* cp   = (float*)(sm + CP_OFF);
    float* coef_s = (float*)(sm + COEF_OFF);
    float* attn_s = (float*)(sm + ATTN_OFF);

    const int tid = threadIdx.x;
    const int wid = tid >> 5;
    const int l   = tid & 31;
    const int mw  = wid >> 2;
    const int nw  = wid & 3;
    const int rg  = l >> 2;
    const int tg  = l & 3;
    const int bid = blockIdx.x;
    const int b64 = (bid >> 6) << 6;
    const int i_g = bid & 63;

    ps[tid]  = g_PQ[(size_t)bid * 512 + tid];
    wcs[tid] = W_coef[tid];

    const float* Ebase = edges + (size_t)bid * 64 * 256;
    const float* W3    = W_in + (size_t)512 * 256;   // [k][n], raw f32

    auto stage = [&](int ch, int buf) {
        uint32_t e_dst = sbase + (buf ? EC1_OFF : EC0_OFF);
        uint32_t w_dst = sbase + (buf ? WC1_OFF : WC0_OFF);
#pragma unroll
        for (int u = 0; u < 2; ++u) {
            int idx = tid * 2 + u;                // 0..511
            int r = idx >> 3, k4 = (idx & 7) << 2;
            CP_ASYNC16(e_dst + (uint32_t)(r * 36 + k4) * 4,
                       Ebase + (size_t)r * 256 + ch * 32 + k4);
        }
        // W: k-major rows ch*32..+32, all 256 n. smem [k][264]
#pragma unroll
        for (int u = 0; u < 8; ++u) {
            int idx = tid + u * 256;              // 0..2047
            int k = idx >> 6, n4 = (idx & 63) << 2;
            CP_ASYNC16(w_dst + (uint32_t)(k * 264 + n4) * 4,
                       W3 + (size_t)(ch * 32 + k) * 256 + n4);
        }
    };

    float acc[2][8][4];
#pragma unroll
    for (int mt = 0; mt < 2; ++mt)
#pragma unroll
        for (int nt = 0; nt < 8; ++nt)
#pragma unroll
            for (int q = 0; q < 4; ++q) acc[mt][nt][q] = 0.f;

    stage(0, 0);
    CP_COMMIT();

    for (int ch = 0; ch < 8; ++ch) {
        if (ch < 7) {
            stage(ch + 1, (ch + 1) & 1);
            CP_COMMIT();
            CP_WAIT1();
        } else {
            CP_WAIT0();
        }
        __syncthreads();

        const uint32_t* EchU = (const uint32_t*)(sm + ((ch & 1) ? EC1_OFF : EC0_OFF));
        const uint32_t* WchU = (const uint32_t*)(sm + ((ch & 1) ? WC1_OFF : WC0_OFF));

#pragma unroll
        for (int k8 = 0; k8 < 4; ++k8) {
            const int kb = k8 * 8;
            uint32_t a[2][4], b[8][2];
#pragma unroll
            for (int mt = 0; mt < 2; ++mt) {
                int r0 = mw * 32 + mt * 16 + rg;
                a[mt][0] = EchU[r0 * 36 + kb + tg];
                a[mt][1] = EchU[(r0 + 8) * 36 + kb + tg];
                a[mt][2] = EchU[r0 * 36 + kb + 4 + tg];
                a[mt][3] = EchU[(r0 + 8) * 36 + kb + 4 + tg];
            }
            const uint32_t* Wk0 = WchU + (kb + tg) * 264;
            const uint32_t* Wk1 = WchU + (kb + 4 + tg) * 264;
#pragma unroll
            for (int nt = 0; nt < 8; ++nt) {
                int n0 = nw * 64 + nt * 8 + rg;
                b[nt][0] = Wk0[n0];
                b[nt][1] = Wk1[n0];
            }
#pragma unroll
            for (int mt = 0; mt < 2; ++mt)
#pragma unroll
                for (int nt = 0; nt < 8; ++nt)
                    mma_tf32(acc[mt][nt], a[mt], b[nt]);
        }
        __syncthreads();
    }

    // ---- epilogue: h = relu(acc + P_i + Q_j) -> hs ----
#pragma unroll
    for (int mt = 0; mt < 2; ++mt) {
        int rA = mw * 32 + mt * 16 + rg;
        int rB = rA + 8;
        const float* qA = g_PQ + (size_t)(b64 + rA) * 512 + 256;
        const float* qB = g_PQ + (size_t)(b64 + rB) * 512 + 256;
#pragma unroll
        for (int nt = 0; nt < 8; ++nt) {
            int c0 = nw * 64 + nt * 8 + tg * 2;
            float2 pv = *(const float2*)(ps + c0);
            float2 qa = *(const float2*)(qA + c0);
            float2 qb = *(const float2*)(qB + c0);
            float h0 = fmaxf(acc[mt][nt][0] + pv.x + qa.x, 0.f);
            float h1 = fmaxf(acc[mt][nt][1] + pv.y + qa.y, 0.f);
            float h2 = fmaxf(acc[mt][nt][2] + pv.x + qb.x, 0.f);
            float h3 = fmaxf(acc[mt][nt][3] + pv.y + qb.y, 0.f);
            *(float2*)(hs + rA * 260 + c0) = make_float2(h0, h1);
            *(float2*)(hs + rB * 260 + c0) = make_float2(h2, h3);
        }
    }
    __syncthreads();

    // ---- h -> gmem ----
    float* hout = out + OUT_H_OFF + (size_t)bid * 64 * 256;
#pragma unroll
    for (int rr = wid * 8; rr < wid * 8 + 8; ++rr) {
#pragma unroll
        for (int q = 0; q < 2; ++q) {
            float4 v = *(const float4*)(hs + rr * 260 + q * 128 + l * 4);
            *(float4*)(hout + (size_t)rr * 256 + q * 128 + l * 4) = v;
        }
    }

    // ---- coef[j] = sum_d h[j][d] * wc[d] ----
    {
        int j = tid & 63, seg = tid >> 6;
        float s = 0.f;
#pragma unroll 8
        for (int d = 0; d < 64; ++d)
            s += hs[j * 260 + seg * 64 + d] * wcs[seg * 64 + d];
        cp[seg * 64 + j] = s;
    }
    __syncthreads();
    if (tid < 64)
        coef_s[tid] = cp[tid] + cp[64 + tid] + cp[128 + tid] + cp[192 + tid]
                    - ((tid == i_g) ? 1e9f : 0.f);
    __syncthreads();

    // ---- softmax ----
    float mval = -3.0e38f;
#pragma unroll 8
    for (int j = 0; j < 64; ++j) mval = fmaxf(mval, coef_s[j]);
    if (tid < 64) attn_s[tid] = __expf(coef_s[tid] - mval);
    __syncthreads();

    float ssum = 0.f;
#pragma unroll 8
    for (int j = 0; j < 64; ++j) ssum += attn_s[j];
    float inv = 1.f / ssum;

    // ---- residual ----
    float r = 0.f;
#pragma unroll 8
    for (int j = 0; j < 64; ++j)
        r += attn_s[j] * hs[j * 260 + tid];
    g_res[(size_t)bid * 256 + tid] = r * inv;
}

// ===========================================================================
// Kernel C: new_nodes = nodes + relu(g_res @ W_out + b_out).
// grid (2,128), K split across block halves. (unchanged)
// ===========================================================================
__global__ __launch_bounds__(256) void finalize3(
    const float* __restrict__ nodes, const float* __restrict__ W_out,
    const float* __restrict__ b_out, float* __restrict__ out)
{
    __shared__ float rs[8 * 256];
    __shared__ float red[8 * 128];
    const int tid = threadIdx.x;
    const int c0 = blockIdx.x * 128;
    const int r0 = blockIdx.y * 8;
    const int lc = tid & 127;
    const int c  = c0 + lc;
    const int kh = tid >> 7;

#pragma unroll
    for (int u = 0; u < 8; ++u)
        rs[u * 256 + tid] = g_res[(size_t)(r0 + u) * 256 + tid];
    __syncthreads();

    float acc[8];
#pragma unroll
    for (int q = 0; q < 8; ++q) acc[q] = 0.f;

    const int kbase = kh * 128;
    const float* Wp = W_out + (size_t)kbase * 256 + c;

#pragma unroll 8
    for (int k4 = 0; k4 < 32; ++k4) {
        float w0 = Wp[(size_t)(k4 * 4 + 0) * 256];
        float w1 = Wp[(size_t)(k4 * 4 + 1) * 256];
        float w2 = Wp[(size_t)(k4 * 4 + 2) * 256];
        float w3 = Wp[(size_t)(k4 * 4 + 3) * 256];
#pragma unroll
        for (int q = 0; q < 8; ++q) {
            float4 rv = *(const float4*)(rs + q * 256 + kbase + k4 * 4);
            acc[q] += rv.x * w0 + rv.y * w1 + rv.z * w2 + rv.w * w3;
        }
    }

    if (kh) {
#pragma unroll
        for (int q = 0; q < 8; ++q) red[q * 128 + lc] = acc[q];
    }
    __syncthreads();
    if (!kh) {
        float bo = b_out[c];
#pragma unroll
        for (int q = 0; q < 8; ++q) {
            float v = acc[q] + red[q * 128 + lc] + bo;
            out[(size_t)(r0 + q) * 256 + c] =
                nodes[(size_t)(r0 + q) * 256 + c] + fmaxf(v, 0.f);
        }
    }
}

// ===========================================================================
extern "C" void kernel_launch(void* const* d_in, const int* in_sizes, int n_in,
                              void* d_out, int out_size) {
    const float* nodes  = (const float*)d_in[0];
    const float* edges  = (const float*)d_in[1];
    const float* W_in   = (const float*)d_in[2];
    const float* b_in   = (const float*)d_in[3];
    const float* W_coef = (const float*)d_in[4];
    // d_in[5] = b_coef: softmax-invariant, skipped
    const float* W_out  = (const float*)d_in[6];
    const float* b_out  = (const float*)d_in[7];
    float* out = (float*)d_out;

    static int smem_set = 0;
    if (!smem_set) {
        cudaFuncSetAttribute(gnn_main6, cudaFuncAttributeMaxDynamicSharedMemorySize, SMEM_BYTES);
        smem_set = 1;
    }

    prep_pq<<<512, 256>>>(nodes, W_in, b_in);
    gnn_main6<<<1024, 256, SMEM_BYTES>>>(edges, W_in, W_coef, out);
    finalize3<<<dim3(2, 128), 256>>>(nodes, W_out, b_out, out);
}

// round 13
// speedup vs baseline: 1.1912x; 1.1912x over previous
#include <cuda_runtime.h>
#include <cuda_fp16.h>
#include <cstdint>

// Shapes fixed: B=16, N=64, D=E=256. Output: [new_nodes 1024x256 | h 65536x256] f32.
#define NROWS     1024
#define OUT_H_OFF (NROWS * 256)

// ---------------- device scratch ----------------
__device__ float    g_PQ[NROWS * 512];    // P = nodes@W1 + b_in | Q = nodes@W2
__device__ uint32_t g_W3p[128 * 256];     // W3 fp16, k-pair packed: [kp][n] = {f16(W3[2kp][n]), f16(W3[2kp+1][n])}
__device__ float    g_res[NROWS * 256];   // attn-weighted residual

// ---------------- helpers ----------------
__device__ __forceinline__ uint32_t pack2h(float lo, float hi) {
    __half2 h = __floats2half2_rn(lo, hi);   // x = lo (element 0), y = hi
    return *(uint32_t*)&h;
}
__device__ __forceinline__ void mma_f16(float* c, const uint32_t* a, const uint32_t* b) {
    asm volatile(
        "mma.sync.aligned.m16n8k16.row.col.f32.f16.f16.f32 "
        "{%0,%1,%2,%3}, {%4,%5,%6,%7}, {%8,%9}, {%0,%1,%2,%3};"
        : "+f"(c[0]), "+f"(c[1]), "+f"(c[2]), "+f"(c[3])
        : "r"(a[0]), "r"(a[1]), "r"(a[2]), "r"(a[3]), "r"(b[0]), "r"(b[1]));
}
__device__ __forceinline__ uint32_t smem_u32(const void* p) {
    uint32_t a;
    asm("{ .reg .u64 t; cvta.to.shared.u64 t, %1; cvt.u32.u64 %0, t; }" : "=r"(a) : "l"(p));
    return a;
}
#define CP_ASYNC16(dst, src) \
    asm volatile("cp.async.cg.shared.global [%0], [%1], 16;" :: "r"(dst), "l"(src))
#define CP_COMMIT()  asm volatile("cp.async.commit_group;" ::: "memory")
#define CP_WAIT1()   asm volatile("cp.async.wait_group 1;" ::: "memory")
#define CP_WAIT0()   asm volatile("cp.async.wait_group 0;" ::: "memory")

// ---------------- smem layout for gnn_main7 (bytes) ----------------
// E tile fp16 [64][40] halves = 5120; W bufs packed u32 [16][264] = 16896 each
#define ESM_OFF   0        // 5120
#define WC0_OFF   5120     // -> 22016
#define WC1_OFF   22016    // -> 38912
#define HS_OFF    0        // epilogue overlay [64][260] f = 66560
#define PS_OFF    66560    // 256 f
#define WCS_OFF   67584    // 256 f
#define CP_OFF    68608    // [4][64] f
#define COEF_OFF  69632    // 64 f
#define ATTN_OFF  69888    // 64 f
#define SMEM_BYTES 70144

// ===========================================================================
// Kernel A (merged prep): blocks 0..255 -> PQ GEMM (32x64 tiles, R10-exact);
// blocks 256..319 -> W3 fp16 k-pair pack. grid 320x256.
// ===========================================================================
__global__ __launch_bounds__(256) void prep(
    const float* __restrict__ nodes, const float* __restrict__ W_in, const float* __restrict__ b_in)
{
    __shared__ float smbuf[64 * 36 + 64 * 64];   // As[64][36] | Bs[64][64]
    const int tid = threadIdx.x;

    if (blockIdx.x >= 256) {
        // ---- W3 -> packed fp16 [kp][n] ----
        const float* W3 = W_in + (size_t)512 * 256;
#pragma unroll
        for (int u = 0; u < 2; ++u) {
            int o = (blockIdx.x - 256) * 512 + u * 256 + tid;   // 0..32767
            int kp = o >> 8, n = o & 255;
            float lo = W3[(size_t)(2 * kp) * 256 + n];
            float hi = W3[(size_t)(2 * kp + 1) * 256 + n];
            g_W3p[o] = pack2h(lo, hi);
        }
        return;
    }

    // ---- PQ = [nodes@W1 + b_in | nodes@W2], 32x64 tile, K=256 in 4 chunks ----
    float* As = smbuf;              // [64][36] (k-major, transposed A)
    float* Bs = smbuf + 64 * 36;    // [64][64]
    const int cb = blockIdx.x & 7;          // 0..7 col block
    const int rb = blockIdx.x >> 3;         // 0..31 row block (32 rows each)
    const int kadd = (cb >= 4) ? 256 : 0;
    const int cbase = (cb & 3) * 64;
    const int ty = tid >> 5;                // warp id 0..7 -> rows ty*4..+3
    const int tx = tid & 31;                // lane -> cols tx*2..+1

    float4 apf[2], bpf[4];
    auto loadA = [&](int kc) {
#pragma unroll
        for (int u = 0; u < 2; ++u) {
            int idx = tid * 2 + u;
            int r = idx >> 4, k4 = (idx & 15) << 2;
            apf[u] = *(const float4*)(nodes + (size_t)(rb * 32 + r) * 256 + kc * 64 + k4);
        }
    };
    auto loadB = [&](int kc) {
#pragma unroll
        for (int u = 0; u < 4; ++u) {
            int idx = tid + u * 256;
            int k = idx >> 4, c4 = (idx & 15) << 2;
            bpf[u] = *(const float4*)(W_in + (size_t)(kadd + kc * 64 + k) * 256 + cbase + c4);
        }
    };

    float acc[4][2];
#pragma unroll
    for (int a = 0; a < 4; ++a) { acc[a][0] = 0.f; acc[a][1] = 0.f; }

    loadA(0);
    loadB(0);

    for (int kc = 0; kc < 4; ++kc) {
#pragma unroll
        for (int u = 0; u < 2; ++u) {
            int idx = tid * 2 + u, r = idx >> 4, k4 = (idx & 15) << 2;
            As[(k4 + 0) * 36 + r] = apf[u].x; As[(k4 + 1) * 36 + r] = apf[u].y;
            As[(k4 + 2) * 36 + r] = apf[u].z; As[(k4 + 3) * 36 + r] = apf[u].w;
        }
#pragma unroll
        for (int u = 0; u < 4; ++u) {
            int idx = tid + u * 256, k = idx >> 4, c4 = (idx & 15) << 2;
            *(float4*)(Bs + k * 64 + c4) = bpf[u];
        }
        __syncthreads();

        if (kc < 3) { loadA(kc + 1); loadB(kc + 1); }

#pragma unroll 8
        for (int kk = 0; kk < 64; ++kk) {
            float4 av = *(const float4*)(As + kk * 36 + ty * 4);
            float2 bv = *(const float2*)(Bs + kk * 64 + tx * 2);
            acc[0][0] += av.x * bv.x; acc[0][1] += av.x * bv.y;
            acc[1][0] += av.y * bv.x; acc[1][1] += av.y * bv.y;
            acc[2][0] += av.z * bv.x; acc[2][1] += av.z * bv.y;
            acc[3][0] += av.w * bv.x; acc[3][1] += av.w * bv.y;
        }
        __syncthreads();
    }

    float2 bias = make_float2(0.f, 0.f);
    if (cb < 4) bias = *(const float2*)(b_in + cbase + tx * 2);
#pragma unroll
    for (int ri = 0; ri < 4; ++ri) {
        int r = rb * 32 + ty * 4 + ri;
        *(float2*)(g_PQ + (size_t)r * 512 + cb * 64 + tx * 2) =
            make_float2(acc[ri][0] + bias.x, acc[ri][1] + bias.y);
    }
}

// ===========================================================================
// Kernel B: fp16 m16n8k16 mma GEMM (H = E@W3 per (b,i)) + fused attention.
// grid 1024, 256 threads. E: LDG->cvt f16x2->STS (reg-prefetched, single buf);
// W: cp.async double-buffered packed fp16 [16][264] u32 (bank-clean).
// C fragment layout identical to m16n8k8 -> epilogue unchanged from R10.
// ===========================================================================
__global__ __launch_bounds__(256) void gnn_main7(
    const float* __restrict__ edges,
    const float* __restrict__ W_coef,
    float* __restrict__ out)
{
    extern __shared__ char sm[];
    const uint32_t sbase = smem_u32(sm);
    float* hs   = (float*)(sm + HS_OFF);
    float* ps   = (float*)(sm + PS_OFF);
    float* wcs  = (float*)(sm + WCS_OFF);
    float* cp   = (float*)(sm + CP_OFF);
    float* coef_s = (float*)(sm + COEF_OFF);
    float* attn_s = (float*)(sm + ATTN_OFF);

    const int tid = threadIdx.x;
    const int wid = tid >> 5;
    const int l   = tid & 31;
    const int mw  = wid >> 2;
    const int nw  = wid & 3;
    const int rg  = l >> 2;
    const int tg  = l & 3;
    const int bid = blockIdx.x;
    const int b64 = (bid >> 6) << 6;
    const int i_g = bid & 63;

    ps[tid]  = g_PQ[(size_t)bid * 512 + tid];
    wcs[tid] = W_coef[tid];

    const float* Ebase = edges + (size_t)bid * 64 * 256;

    // ---- E staging: LDG float4 x2 -> 4x f16x2 -> one STS.128 ----
    const int er = tid >> 2;              // row 0..63
    const int ek = (tid & 3) * 8;         // k offset within 32-chunk
    float4 epf0, epf1;
    auto loadE = [&](int ch) {
        const float* p = Ebase + (size_t)er * 256 + ch * 32 + ek;
        epf0 = *(const float4*)p;
        epf1 = *(const float4*)(p + 4);
    };
    auto stsE = [&]() {
        uint4 u;
        u.x = pack2h(epf0.x, epf0.y);
        u.y = pack2h(epf0.z, epf0.w);
        u.z = pack2h(epf1.x, epf1.y);
        u.w = pack2h(epf1.z, epf1.w);
        *(uint4*)(sm + ESM_OFF + (er * 40 + ek) * 2) = u;   // halves -> bytes
    };

    // ---- W staging: cp.async packed u32, [16][264] ----
    auto stageW = [&](int ch, int buf) {
        uint32_t w_dst = sbase + (buf ? WC1_OFF : WC0_OFF);
#pragma unroll
        for (int u = 0; u < 4; ++u) {
            int idx = tid + u * 256;              // 0..1023
            int kp = idx >> 6, n4 = (idx & 63) << 2;
            CP_ASYNC16(w_dst + (uint32_t)(kp * 264 + n4) * 4,
                       g_W3p + (size_t)(ch * 16 + kp) * 256 + n4);
        }
    };

    float acc[2][8][4];
#pragma unroll
    for (int mt = 0; mt < 2; ++mt)
#pragma unroll
        for (int nt = 0; nt < 8; ++nt)
#pragma unroll
            for (int q = 0; q < 4; ++q) acc[mt][nt][q] = 0.f;

    loadE(0);
    stageW(0, 0);
    CP_COMMIT();

    for (int ch = 0; ch < 8; ++ch) {
        stsE();                                   // prev compute done (trailing sync)
        if (ch < 7) {
            stageW(ch + 1, (ch + 1) & 1);
            CP_COMMIT();
            CP_WAIT1();                           // W(ch) arrived
        } else {
            CP_WAIT0();
        }
        __syncthreads();

        if (ch < 7) loadE(ch + 1);                // latency hidden by compute

        const uint32_t* EchU = (const uint32_t*)(sm + ESM_OFF);
        const uint32_t* WchU = (const uint32_t*)(sm + ((ch & 1) ? WC1_OFF : WC0_OFF));

#pragma unroll
        for (int s = 0; s < 2; ++s) {             // two k16 steps per 32-chunk
            const int kh = s * 8;                 // u32 (k-pair) base
            uint32_t a[2][4], b[8][2];
#pragma unroll
            for (int mt = 0; mt < 2; ++mt) {
                int r0 = mw * 32 + mt * 16 + rg;
                a[mt][0] = EchU[r0 * 20 + kh + tg];
                a[mt][1] = EchU[(r0 + 8) * 20 + kh + tg];
                a[mt][2] = EchU[r0 * 20 + kh + tg + 4];
                a[mt][3] = EchU[(r0 + 8) * 20 + kh + tg + 4];
            }
            const uint32_t* Wk0 = WchU + (kh + tg) * 264;
            const uint32_t* Wk1 = WchU + (kh + tg + 4) * 264;
#pragma unroll
            for (int nt = 0; nt < 8; ++nt) {
                int n0 = nw * 64 + nt * 8 + rg;
                b[nt][0] = Wk0[n0];
                b[nt][1] = Wk1[n0];
            }
#pragma unroll
            for (int mt = 0; mt < 2; ++mt)
#pragma unroll
                for (int nt = 0; nt < 8; ++nt)
                    mma_f16(acc[mt][nt], a[mt], b[nt]);
        }
        __syncthreads();
    }

    // ---- epilogue: h = relu(acc + P_i + Q_j) -> hs (identical to R10) ----
#pragma unroll
    for (int mt = 0; mt < 2; ++mt) {
        int rA = mw * 32 + mt * 16 + rg;
        int rB = rA + 8;
        const float* qA = g_PQ + (size_t)(b64 + rA) * 512 + 256;
        const float* qB = g_PQ + (size_t)(b64 + rB) * 512 + 256;
#pragma unroll
        for (int nt = 0; nt < 8; ++nt) {
            int c0 = nw * 64 + nt * 8 + tg * 2;
            float2 pv = *(const float2*)(ps + c0);
            float2 qa = *(const float2*)(qA + c0);
            float2 qb = *(const float2*)(qB + c0);
            float h0 = fmaxf(acc[mt][nt][0] + pv.x + qa.x, 0.f);
            float h1 = fmaxf(acc[mt][nt][1] + pv.y + qa.y, 0.f);
            float h2 = fmaxf(acc[mt][nt][2] + pv.x + qb.x, 0.f);
            float h3 = fmaxf(acc[mt][nt][3] + pv.y + qb.y, 0.f);
            *(float2*)(hs + rA * 260 + c0) = make_float2(h0, h1);
            *(float2*)(hs + rB * 260 + c0) = make_float2(h2, h3);
        }
    }
    __syncthreads();

    // ---- h -> gmem ----
    float* hout = out + OUT_H_OFF + (size_t)bid * 64 * 256;
#pragma unroll
    for (int rr = wid * 8; rr < wid * 8 + 8; ++rr) {
#pragma unroll
        for (int q = 0; q < 2; ++q) {
            float4 v = *(const float4*)(hs + rr * 260 + q * 128 + l * 4);
            *(float4*)(hout + (size_t)rr * 256 + q * 128 + l * 4) = v;
        }
    }

    // ---- coef[j] = sum_d h[j][d] * wc[d] ----
    {
        int j = tid & 63, seg = tid >> 6;
        float s = 0.f;
#pragma unroll 8
        for (int d = 0; d < 64; ++d)
            s += hs[j * 260 + seg * 64 + d] * wcs[seg * 64 + d];
        cp[seg * 64 + j] = s;
    }
    __syncthreads();
    if (tid < 64)
        coef_s[tid] = cp[tid] + cp[64 + tid] + cp[128 + tid] + cp[192 + tid]
                    - ((tid == i_g) ? 1e9f : 0.f);
    __syncthreads();

    // ---- softmax ----
    float mval = -3.0e38f;
#pragma unroll 8
    for (int j = 0; j < 64; ++j) mval = fmaxf(mval, coef_s[j]);
    if (tid < 64) attn_s[tid] = __expf(coef_s[tid] - mval);
    __syncthreads();

    float ssum = 0.f;
#pragma unroll 8
    for (int j = 0; j < 64; ++j) ssum += attn_s[j];
    float inv = 1.f / ssum;

    // ---- residual ----
    float r = 0.f;
#pragma unroll 8
    for (int j = 0; j < 64; ++j)
        r += attn_s[j] * hs[j * 260 + tid];
    g_res[(size_t)bid * 256 + tid] = r * inv;
}

// ===========================================================================
// Kernel C: new_nodes = nodes + relu(g_res @ W_out + b_out).
// grid (2,128), K split across block halves. (unchanged)
// ===========================================================================
__global__ __launch_bounds__(256) void finalize3(
    const float* __restrict__ nodes, const float* __restrict__ W_out,
    const float* __restrict__ b_out, float* __restrict__ out)
{
    __shared__ float rs[8 * 256];
    __shared__ float red[8 * 128];
    const int tid = threadIdx.x;
    const int c0 = blockIdx.x * 128;
    const int r0 = blockIdx.y * 8;
    const int lc = tid & 127;
    const int c  = c0 + lc;
    const int kh = tid >> 7;

#pragma unroll
    for (int u = 0; u < 8; ++u)
        rs[u * 256 + tid] = g_res[(size_t)(r0 + u) * 256 + tid];
    __syncthreads();

    float acc[8];
#pragma unroll
    for (int q = 0; q < 8; ++q) acc[q] = 0.f;

    const int kbase = kh * 128;
    const float* Wp = W_out + (size_t)kbase * 256 + c;

#pragma unroll 8
    for (int k4 = 0; k4 < 32; ++k4) {
        float w0 = Wp[(size_t)(k4 * 4 + 0) * 256];
        float w1 = Wp[(size_t)(k4 * 4 + 1) * 256];
        float w2 = Wp[(size_t)(k4 * 4 + 2) * 256];
        float w3 = Wp[(size_t)(k4 * 4 + 3) * 256];
#pragma unroll
        for (int q = 0; q < 8; ++q) {
            float4 rv = *(const float4*)(rs + q * 256 + kbase + k4 * 4);
            acc[q] += rv.x * w0 + rv.y * w1 + rv.z * w2 + rv.w * w3;
        }
    }

    if (kh) {
#pragma unroll
        for (int q = 0; q < 8; ++q) red[q * 128 + lc] = acc[q];
    }
    __syncthreads();
    if (!kh) {
        float bo = b_out[c];
#pragma unroll
        for (int q = 0; q < 8; ++q) {
            float v = acc[q] + red[q * 128 + lc] + bo;
            out[(size_t)(r0 + q) * 256 + c] =
                nodes[(size_t)(r0 + q) * 256 + c] + fmaxf(v, 0.f);
        }
    }
}

// ===========================================================================
extern "C" void kernel_launch(void* const* d_in, const int* in_sizes, int n_in,
                              void* d_out, int out_size) {
    const float* nodes  = (const float*)d_in[0];
    const float* edges  = (const float*)d_in[1];
    const float* W_in   = (const float*)d_in[2];
    const float* b_in   = (const float*)d_in[3];
    const float* W_coef = (const float*)d_in[4];
    // d_in[5] = b_coef: softmax-invariant, skipped
    const float* W_out  = (const float*)d_in[6];
    const float* b_out  = (const float*)d_in[7];
    float* out = (float*)d_out;

    static int smem_set = 0;
    if (!smem_set) {
        cudaFuncSetAttribute(gnn_main7, cudaFuncAttributeMaxDynamicSharedMemorySize, SMEM_BYTES);
        smem_set = 1;
    }

    prep<<<320, 256>>>(nodes, W_in, b_in);
    gnn_main7<<<1024, 256, SMEM_BYTES>>>(edges, W_coef, out);
    finalize3<<<dim3(2, 128), 256>>>(nodes, W_out, b_out, out);
}